// round 2
// baseline (speedup 1.0000x reference)
#include <cuda_runtime.h>
#include <math.h>

#define B_ 16
#define N_ 64
#define E_ 512
#define C_ 512
#define H1_ 256
#define H2_ 128
#define H3_ 64
#define U_ 8
#define R_ 8
#define EH_ 64
#define EPS_ 1e-5f
#define NODE_OUT (B_*N_*N_*U_)   /* 524288 */

__device__ __align__(16) float g_x1[B_*N_*H1_];
__device__ __align__(16) float g_x2[B_*N_*H2_];
__device__ __align__(16) float g_x3[B_*N_*H3_];
__device__ __align__(16) float g_nodec[B_*N_*U_];
__device__ __align__(16) float g_P[B_*N_*EH_];
__device__ __align__(16) float g_Q[B_*N_*EH_];
__device__ __align__(16) float g_rel[B_*N_*N_*R_];
__device__ int g_see[B_*N_*N_];
__device__ int g_cnt[B_*N_];

// ---------------------------------------------------------------------------
// 1. Build see-table + counts. One block per batch, one thread per dst node.
// ---------------------------------------------------------------------------
__global__ void __launch_bounds__(64)
build_see_kernel(const int* __restrict__ edge_index) {
    __shared__ int sdst[E_];
    __shared__ int ssrc[E_];
    int b = blockIdx.x, n = threadIdx.x;
    const int* src = edge_index + b * 2 * E_;
    const int* dst = src + E_;
    for (int l = n; l < E_; l += 64) { ssrc[l] = src[l]; sdst[l] = dst[l]; }
    __syncthreads();
    int* row = g_see + (b * N_ + n) * N_;
    #pragma unroll 8
    for (int j = 0; j < N_; j++) row[j] = 0;
    row[0] = n;
    int c = 0;
    #pragma unroll 8
    for (int e = 0; e < E_; e++) {
        if (sdst[e] == n) {
            c++;
            if (c < N_) row[c] = ssrc[e];   // pos >= N dropped (mode='drop')
        }
    }
    g_cnt[b * N_ + n] = min(c + 1, N_);
}

// ---------------------------------------------------------------------------
// 2. Register-tiled SGEMM with fused epilogue.
//    EPI 0: relu(BN(x@W + bias));  EPI 1: relu(x@W + bias)
// ---------------------------------------------------------------------------
template<int BM, int BN, int EPI>
__global__ void __launch_bounds__((BM/4)*(BN/4))
gemm_kernel(const float* __restrict__ A, const float* __restrict__ W,
            float* __restrict__ C, int M, int Nc, int K,
            const float* __restrict__ bias,
            const float* __restrict__ gam, const float* __restrict__ bet,
            const float* __restrict__ mu,  const float* __restrict__ var)
{
    const int BK = 16;
    const int NTHR = (BM/4)*(BN/4);
    __shared__ __align__(16) float As[BK * (BM + 4)];
    __shared__ __align__(16) float Bs[BK * BN];
    int tid = threadIdx.x;
    int tc = tid % (BN/4);
    int tr = tid / (BN/4);
    int bm = blockIdx.y * BM;
    int bn = blockIdx.x * BN;
    float acc[4][4] = {};
    for (int k0 = 0; k0 < K; k0 += BK) {
        #pragma unroll
        for (int l = tid; l < BM*BK/4; l += NTHR) {
            int m  = l / (BK/4);
            int kk = (l % (BK/4)) * 4;
            float4 v = *reinterpret_cast<const float4*>(&A[(size_t)(bm+m)*K + k0 + kk]);
            As[(kk+0)*(BM+4)+m] = v.x;
            As[(kk+1)*(BM+4)+m] = v.y;
            As[(kk+2)*(BM+4)+m] = v.z;
            As[(kk+3)*(BM+4)+m] = v.w;
        }
        #pragma unroll
        for (int l = tid; l < BK*BN/4; l += NTHR) {
            int k  = l / (BN/4);
            int nn = (l % (BN/4)) * 4;
            *reinterpret_cast<float4*>(&Bs[k*BN+nn]) =
                *reinterpret_cast<const float4*>(&W[(size_t)(k0+k)*Nc + bn + nn]);
        }
        __syncthreads();
        #pragma unroll
        for (int k = 0; k < BK; k++) {
            float4 av = *reinterpret_cast<const float4*>(&As[k*(BM+4) + tr*4]);
            float4 bv = *reinterpret_cast<const float4*>(&Bs[k*BN + tc*4]);
            float a[4] = {av.x, av.y, av.z, av.w};
            float w[4] = {bv.x, bv.y, bv.z, bv.w};
            #pragma unroll
            for (int i = 0; i < 4; i++)
                #pragma unroll
                for (int j = 0; j < 4; j++)
                    acc[i][j] = fmaf(a[i], w[j], acc[i][j]);
        }
        __syncthreads();
    }
    #pragma unroll
    for (int i = 0; i < 4; i++) {
        int m = bm + tr*4 + i;
        float4 o;
        float* op = &o.x;
        #pragma unroll
        for (int j = 0; j < 4; j++) {
            int n = bn + tc*4 + j;
            float v = acc[i][j] + bias[n];
            if (EPI == 0) {
                float sc = gam[n] * rsqrtf(var[n] + EPS_);
                v = (v - mu[n]) * sc + bet[n];
            }
            op[j] = fmaxf(v, 0.0f);
        }
        *reinterpret_cast<float4*>(&C[(size_t)m*Nc + bn + tc*4]) = o;
    }
}

// ---------------------------------------------------------------------------
// 3. Node head: node_c = sigmoid(x3 @ wn + bn_c)   (1024 x 8, K=64)
// ---------------------------------------------------------------------------
__global__ void node_head_kernel(const float* __restrict__ wn,
                                 const float* __restrict__ bn_c) {
    int gid = blockIdx.x * blockDim.x + threadIdx.x;  // B*N*U = 8192
    if (gid >= B_*N_*U_) return;
    int row = gid >> 3, u = gid & 7;
    const float* xr = g_x3 + row * H3_;
    float s = bn_c[u];
    #pragma unroll 8
    for (int k = 0; k < H3_; k++) s = fmaf(xr[k], wn[k*U_ + u], s);
    g_nodec[gid] = 1.0f / (1.0f + expf(-s));
}

// ---------------------------------------------------------------------------
// 4. Edge layer-1 factorization: P = attr@we1[:9] + be1,  Q = attr@we1[9:]
// ---------------------------------------------------------------------------
__global__ void edge_pq_kernel(const float* __restrict__ bbox,
                               const float* __restrict__ dir,
                               const float* __restrict__ prio,
                               const float* __restrict__ we1,
                               const float* __restrict__ be1) {
    int gid = blockIdx.x * blockDim.x + threadIdx.x;  // B*N*EH = 65536
    if (gid >= B_*N_*EH_) return;
    int row = gid >> 6, h = gid & 63;
    const float inv = 1.0f / 1024.0f;
    float a[9];
    #pragma unroll
    for (int c = 0; c < 4; c++) a[c]   = bbox[row*4+c] * inv;
    #pragma unroll
    for (int c = 0; c < 4; c++) a[4+c] = dir[row*4+c];
    a[8] = prio[row];
    float p = be1[h], q = 0.0f;
    #pragma unroll
    for (int c = 0; c < 9; c++) {
        p = fmaf(a[c], we1[c*EH_ + h], p);
        q = fmaf(a[c], we1[(9+c)*EH_ + h], q);
    }
    g_P[gid] = p;
    g_Q[gid] = q;
}

// ---------------------------------------------------------------------------
// 5. Fused edge MLP: per (b,i) block compute e1 (smem) -> e2 (regs/smem) ->
//    rel[b,i,:,:] = sigmoid(e2 @ wei + bei). 1024 blocks x 256 threads.
// ---------------------------------------------------------------------------
__global__ void __launch_bounds__(256)
edge_fused_kernel(const float* __restrict__ we2, const float* __restrict__ be2,
                  const float* __restrict__ wei, const float* __restrict__ bei) {
    const int LD = 68;
    __shared__ __align__(16) float sE1[64*LD];   // phase 1: [h][j]; phase 2 reused as e2 [j][o]
    __shared__ __align__(16) float sW2[64*LD];   // [h][o]
    __shared__ float sP[64], sBe2[64], sWei[64*8], sBei[8];
    int tid = threadIdx.x;
    int bi = blockIdx.x;          // b*64 + i
    int b = bi >> 6;

    if (tid < 64) { sP[tid] = g_P[bi*64 + tid]; sBe2[tid] = be2[tid]; }
    if (tid < 8) sBei[tid] = bei[tid];
    for (int l = tid; l < 512; l += 256) sWei[l] = wei[l];
    for (int l = tid; l < 1024; l += 256) {
        float4 v = reinterpret_cast<const float4*>(we2)[l];
        int h = l >> 4, o = (l & 15) * 4;
        *reinterpret_cast<float4*>(&sW2[h*LD + o]) = v;
    }
    __syncthreads();

    // e1[h][j] = relu(P[b,i,h] + Q[b,j,h])
    const float4* Qb = reinterpret_cast<const float4*>(g_Q + b * N_ * EH_);
    for (int l = tid; l < 1024; l += 256) {
        float4 qv = Qb[l];
        int j = l >> 4, h0 = (l & 15) * 4;
        sE1[(h0+0)*LD + j] = fmaxf(sP[h0+0] + qv.x, 0.0f);
        sE1[(h0+1)*LD + j] = fmaxf(sP[h0+1] + qv.y, 0.0f);
        sE1[(h0+2)*LD + j] = fmaxf(sP[h0+2] + qv.z, 0.0f);
        sE1[(h0+3)*LD + j] = fmaxf(sP[h0+3] + qv.w, 0.0f);
    }
    __syncthreads();

    // e2[j][o] = relu(sum_h e1[j][h] * we2[h][o] + be2[o]); 4x4 per thread
    int tc = tid & 15, tr = tid >> 4;
    float acc[4][4] = {};
    #pragma unroll
    for (int h = 0; h < 64; h++) {
        float4 av = *reinterpret_cast<const float4*>(&sE1[h*LD + tr*4]);
        float4 bv = *reinterpret_cast<const float4*>(&sW2[h*LD + tc*4]);
        float a[4] = {av.x, av.y, av.z, av.w};
        float w[4] = {bv.x, bv.y, bv.z, bv.w};
        #pragma unroll
        for (int i = 0; i < 4; i++)
            #pragma unroll
            for (int j = 0; j < 4; j++)
                acc[i][j] = fmaf(a[i], w[j], acc[i][j]);
    }
    __syncthreads();   // everyone done reading e1 before overwrite
    #pragma unroll
    for (int i = 0; i < 4; i++)
        #pragma unroll
        for (int c = 0; c < 4; c++)
            sE1[(tr*4+i)*LD + tc*4 + c] = fmaxf(acc[i][c] + sBe2[tc*4+c], 0.0f);
    __syncthreads();

    // rel[j][r] = sigmoid(sum_o e2[j][o]*wei[o][r] + bei[r]); thread -> (j, 2 r's)
    int j = tid >> 2, r2 = tid & 3;
    float a0 = sBei[r2*2], a1 = sBei[r2*2+1];
    #pragma unroll 16
    for (int o = 0; o < 64; o++) {
        float e = sE1[j*LD + o];
        a0 = fmaf(e, sWei[o*8 + r2*2],     a0);
        a1 = fmaf(e, sWei[o*8 + r2*2 + 1], a1);
    }
    float2 out;
    out.x = 1.0f / (1.0f + expf(-a0));
    out.y = 1.0f / (1.0f + expf(-a1));
    *reinterpret_cast<float2*>(&g_rel[(bi*64 + j)*8 + r2*2]) = out;
}

// ---------------------------------------------------------------------------
// 6. node_concepts gather (writes first 524288 floats of out)
// ---------------------------------------------------------------------------
__global__ void node_gather_kernel(float* __restrict__ out) {
    int gid = blockIdx.x * blockDim.x + threadIdx.x;  // B*N*N = 65536
    if (gid >= B_*N_*N_) return;
    int j  = gid & 63;
    int bi = gid >> 6;
    int b  = gid >> 12;
    int s  = g_see[gid];
    float msk = (j < g_cnt[bi]) ? 1.0f : 0.0f;
    const float4* np = reinterpret_cast<const float4*>(g_nodec + (b*N_ + s)*U_);
    float4 v0 = np[0], v1 = np[1];
    v0.x *= msk; v0.y *= msk; v0.z *= msk; v0.w *= msk;
    v1.x *= msk; v1.y *= msk; v1.z *= msk; v1.w *= msk;
    float4* op = reinterpret_cast<float4*>(out + (size_t)gid * U_);
    op[0] = v0; op[1] = v1;
}

// ---------------------------------------------------------------------------
// 7. edge_concepts gather: out[bi, j, k, :] = rel[b, see[j], see[k], :]*m_j*m_k
// ---------------------------------------------------------------------------
__global__ void __launch_bounds__(256)
edge_gather_kernel(float* __restrict__ out) {
    int bi = blockIdx.x;
    int b  = bi >> 6;
    __shared__ int   ss[64];
    __shared__ float sm[64];
    int tid = threadIdx.x;
    if (tid < 64) {
        ss[tid] = g_see[bi*64 + tid];
        sm[tid] = (tid < g_cnt[bi]) ? 1.0f : 0.0f;
    }
    __syncthreads();
    float* outE = out + (size_t)NODE_OUT + (size_t)bi * (N_*N_*R_);
    const float* relb = g_rel + b * (N_*N_*R_);
    #pragma unroll
    for (int it = 0; it < 16; it++) {
        int idx = tid + 256*it;
        int j = idx >> 6, k = idx & 63;
        float m = sm[j] * sm[k];
        const float4* rp = reinterpret_cast<const float4*>(relb + (ss[j]*N_ + ss[k])*R_);
        float4 v0 = rp[0], v1 = rp[1];
        v0.x *= m; v0.y *= m; v0.z *= m; v0.w *= m;
        v1.x *= m; v1.y *= m; v1.z *= m; v1.w *= m;
        float4* op = reinterpret_cast<float4*>(outE + (size_t)idx * R_);
        op[0] = v0; op[1] = v1;
    }
}

// ---------------------------------------------------------------------------
extern "C" void kernel_launch(void* const* d_in, const int* in_sizes, int n_in,
                              void* d_out, int out_size) {
    const float* roi  = (const float*)d_in[0];
    const float* bbox = (const float*)d_in[1];
    const float* dir  = (const float*)d_in[2];
    const float* prio = (const float*)d_in[3];
    const float* w1   = (const float*)d_in[4];
    const float* b1   = (const float*)d_in[5];
    const float* g1   = (const float*)d_in[6];
    const float* bt1  = (const float*)d_in[7];
    const float* m1   = (const float*)d_in[8];
    const float* v1   = (const float*)d_in[9];
    const float* w2   = (const float*)d_in[10];
    const float* b2   = (const float*)d_in[11];
    const float* g2   = (const float*)d_in[12];
    const float* bt2  = (const float*)d_in[13];
    const float* m2   = (const float*)d_in[14];
    const float* v2   = (const float*)d_in[15];
    const float* w3   = (const float*)d_in[16];
    const float* b3   = (const float*)d_in[17];
    const float* wn   = (const float*)d_in[18];
    const float* bnc  = (const float*)d_in[19];
    const float* we1  = (const float*)d_in[20];
    const float* be1  = (const float*)d_in[21];
    const float* we2  = (const float*)d_in[22];
    const float* be2  = (const float*)d_in[23];
    const float* wei  = (const float*)d_in[24];
    const float* bei  = (const float*)d_in[25];
    const int*   eidx = (const int*)d_in[26];
    float* out = (float*)d_out;

    void *px1 = 0, *px2 = 0, *px3 = 0;
    cudaGetSymbolAddress(&px1, g_x1);
    cudaGetSymbolAddress(&px2, g_x2);
    cudaGetSymbolAddress(&px3, g_x3);

    build_see_kernel<<<B_, 64>>>(eidx);

    gemm_kernel<32,64,0><<<dim3(H1_/64, (B_*N_)/32), 128>>>(
        roi, w1, (float*)px1, B_*N_, H1_, C_, b1, g1, bt1, m1, v1);
    gemm_kernel<32,64,0><<<dim3(H2_/64, (B_*N_)/32), 128>>>(
        (const float*)px1, w2, (float*)px2, B_*N_, H2_, H1_, b2, g2, bt2, m2, v2);
    gemm_kernel<32,64,1><<<dim3(H3_/64, (B_*N_)/32), 128>>>(
        (const float*)px2, w3, (float*)px3, B_*N_, H3_, H2_, b3, 0, 0, 0, 0);

    node_head_kernel<<<(B_*N_*U_)/256, 256>>>(wn, bnc);
    edge_pq_kernel<<<(B_*N_*EH_)/256, 256>>>(bbox, dir, prio, we1, be1);
    edge_fused_kernel<<<B_*N_, 256>>>(we2, be2, wei, bei);

    node_gather_kernel<<<(B_*N_*N_)/256, 256>>>(out);
    edge_gather_kernel<<<B_*N_, 256>>>(out);
}